// round 1
// baseline (speedup 1.0000x reference)
#include <cuda_runtime.h>

// Problem constants: B*C = 16, L = 128, N = 48
#define BC 16

// Scratch buffers (device globals — no allocation allowed in kernel_launch)
__device__ float g_bufA[(size_t)BC * 16384 * 48]; // 12.58M floats (stage1 / stage5 out)
__device__ float g_bufB[(size_t)BC * 6144  * 48]; // 4.72M floats  (stage2 / stage4 out)
__device__ float g_bufC[(size_t)BC * 2304  * 48]; // 1.77M floats  (enc)

// Generic "contract leading axis" kernel:
//   out[b][j][m0+m] = sum_k W[k][m0+m] * in[b][k][j]
// in:  [batch][K][J]  (j contiguous)
// W:   [K][M]         (m contiguous)
// out: [batch][J][M]  (m contiguous)
// grid = (J/128, M/MCHUNK, batch), block = 128 threads, thread owns one j.
template<int K, int M, int MCHUNK>
__global__ void __launch_bounds__(128) contract_lead(
    const float* __restrict__ in, const float* __restrict__ W,
    float* __restrict__ out, int J)
{
    constexpr int TJ = 128;
    const int b  = blockIdx.z;
    const int m0 = blockIdx.y * MCHUNK;
    const int j  = blockIdx.x * TJ + threadIdx.x;

    __shared__ float Ws[K * MCHUNK];
    for (int idx = threadIdx.x; idx < K * MCHUNK; idx += TJ) {
        int k = idx / MCHUNK;
        int m = idx % MCHUNK;
        Ws[idx] = W[k * M + m0 + m];
    }
    __syncthreads();

    const float* inp = in + (size_t)b * K * J + j;

    float acc[MCHUNK];
#pragma unroll
    for (int m = 0; m < MCHUNK; m++) acc[m] = 0.0f;

#pragma unroll 4
    for (int k = 0; k < K; k++) {
        float v = __ldg(inp + (size_t)k * J);
        const float4* w4 = reinterpret_cast<const float4*>(&Ws[k * MCHUNK]);
#pragma unroll
        for (int mv = 0; mv < MCHUNK / 4; mv++) {
            float4 w = w4[mv];
            acc[4*mv+0] += w.x * v;
            acc[4*mv+1] += w.y * v;
            acc[4*mv+2] += w.z * v;
            acc[4*mv+3] += w.w * v;
        }
    }

    float* op = out + (size_t)b * J * M + (size_t)j * M + m0;
#pragma unroll
    for (int mv = 0; mv < MCHUNK / 4; mv++) {
        reinterpret_cast<float4*>(op)[mv] =
            make_float4(acc[4*mv+0], acc[4*mv+1], acc[4*mv+2], acc[4*mv+3]);
    }
}

extern "C" void kernel_launch(void* const* d_in, const int* in_sizes, int n_in,
                              void* d_out, int out_size)
{
    const float* x   = (const float*)d_in[0];
    const float* EN3 = (const float*)d_in[1];
    const float* EN2 = (const float*)d_in[2];
    const float* EN1 = (const float*)d_in[3];
    const float* DE3 = (const float*)d_in[4];
    const float* DE2 = (const float*)d_in[5];
    const float* DE1 = (const float*)d_in[6];
    float* out = (float*)d_out;

    float *bufA, *bufB, *bufC;
    cudaGetSymbolAddress((void**)&bufA, g_bufA);
    cudaGetSymbolAddress((void**)&bufB, g_bufB);
    cudaGetSymbolAddress((void**)&bufC, g_bufC);

    // ---- Encode (K=128, M=48) ----
    // S1: contract d.  x[bc][d][h,w] (J=16384) -> bufA = [bc][h][w][p]
    contract_lead<128, 48, 48><<<dim3(128, 1, BC), 128>>>(x, EN3, bufA, 16384);
    // S2: contract h.  bufA[bc][h][w,p] (J=6144) -> bufB = [bc][w][p][q]
    contract_lead<128, 48, 48><<<dim3(48, 1, BC), 128>>>(bufA, EN2, bufB, 6144);
    // S3: contract w.  bufB[bc][w][p,q] (J=2304) -> bufC = enc = [bc][p][q][r]
    contract_lead<128, 48, 48><<<dim3(18, 1, BC), 128>>>(bufB, EN1, bufC, 2304);

    // ---- Decode (K=48, M=128); single ordering == averaged result exactly ----
    // S4: contract p.  enc[bc][p][q,r] (J=2304) -> bufB = [bc][q][r][d]
    contract_lead<48, 128, 64><<<dim3(18, 2, BC), 128>>>(bufC, DE3, bufB, 2304);
    // S5: contract q.  bufB[bc][q][r,d] (J=6144) -> bufA = [bc][r][d][h]
    contract_lead<48, 128, 64><<<dim3(48, 2, BC), 128>>>(bufB, DE2, bufA, 6144);
    // S6: contract r.  bufA[bc][r][d,h] (J=16384) -> out = [b][c][d][h][w]
    contract_lead<48, 128, 64><<<dim3(128, 2, BC), 128>>>(bufA, DE1, out, 16384);
}

// round 2
// speedup vs baseline: 1.2087x; 1.2087x over previous
#include <cuda_runtime.h>

// Problem constants: B*C = 16, L = 128, N = 48
#define BC 16

// Scratch buffers (device globals — allocation in kernel_launch is forbidden)
__device__ float g_bufA[(size_t)BC * 16384 * 48]; // stage1 / stage5 out
__device__ float g_bufB[(size_t)BC * 6144  * 48]; // stage2 / stage4 out
__device__ float g_bufC[(size_t)BC * 2304  * 48]; // enc

// Register-tiled GEMM for "contract leading axis":
//   out[b][j][m] = sum_k in[b][k][j] * W[k][m]
// in : [batch][K][J]  (j contiguous)
// W  : [K][M]         (m contiguous)   -- fully staged in smem
// out: [batch][J][M]  (m contiguous)
//
// Block: TX*TY threads computes BJ=TX*TJ j's  x  full M (=TY*TM).
// A streamed through smem in KB-panels.
// grid = (J/BJ, 1, batch)
template<int K, int M, int KB, int TX, int TY, int TJ, int TM>
__global__ void __launch_bounds__(TX * TY) gemm_stage(
    const float* __restrict__ in, const float* __restrict__ W,
    float* __restrict__ out, int J)
{
    constexpr int BJ = TX * TJ;
    constexpr int NT = TX * TY;

    __shared__ float Ws[K * M];
    __shared__ float As[KB][BJ];

    const int tid = threadIdx.x;
    const int tx  = tid % TX;          // j-tile index
    const int ty  = tid / TX;          // m-tile index
    const int b   = blockIdx.z;
    const int j0  = blockIdx.x * BJ;

    // ---- stage full W into smem (K*M floats, vectorized, exact multiple) ----
#pragma unroll
    for (int i = tid * 4; i < K * M; i += NT * 4) {
        *reinterpret_cast<float4*>(&Ws[i]) =
            *reinterpret_cast<const float4*>(&W[i]);
    }

    const float* inb = in + (size_t)b * K * J + j0;

    float acc[TJ][TM];
#pragma unroll
    for (int i = 0; i < TJ; i++)
#pragma unroll
        for (int t = 0; t < TM; t++) acc[i][t] = 0.0f;

#pragma unroll 1
    for (int kp = 0; kp < K; kp += KB) {
        __syncthreads();   // protect Ws (1st iter) / As reuse (later iters)
        // ---- load A panel: KB x BJ floats, fully coalesced float4 ----
#pragma unroll
        for (int idx = tid; idx < KB * BJ / 4; idx += NT) {
            const int row = idx / (BJ / 4);
            const int col = (idx % (BJ / 4)) * 4;
            *reinterpret_cast<float4*>(&As[row][col]) =
                *reinterpret_cast<const float4*>(&inb[(size_t)(kp + row) * J + col]);
        }
        __syncthreads();

        // ---- outer-product accumulate ----
#pragma unroll 4
        for (int kk = 0; kk < KB; kk++) {
            float a[TJ], bw[TM];
#pragma unroll
            for (int i = 0; i < TJ; i += 4) {
                float4 v = *reinterpret_cast<const float4*>(&As[kk][tx * TJ + i]);
                a[i] = v.x; a[i + 1] = v.y; a[i + 2] = v.z; a[i + 3] = v.w;
            }
            const float* wrow = &Ws[(kp + kk) * M + ty * TM];
#pragma unroll
            for (int t = 0; t < TM; t += 2) {
                float2 v = *reinterpret_cast<const float2*>(&wrow[t]);
                bw[t] = v.x; bw[t + 1] = v.y;
            }
#pragma unroll
            for (int i = 0; i < TJ; i++)
#pragma unroll
                for (int t = 0; t < TM; t++)
                    acc[i][t] += a[i] * bw[t];
        }
    }

    // ---- write out: [b][j][m], m contiguous ----
    float* op = out + (size_t)b * J * M + (size_t)(j0 + tx * TJ) * M + ty * TM;
#pragma unroll
    for (int i = 0; i < TJ; i++) {
#pragma unroll
        for (int t = 0; t < TM; t += 2) {
            *reinterpret_cast<float2*>(&op[(size_t)i * M + t]) =
                make_float2(acc[i][t], acc[i][t + 1]);
        }
    }
}

extern "C" void kernel_launch(void* const* d_in, const int* in_sizes, int n_in,
                              void* d_out, int out_size)
{
    const float* x   = (const float*)d_in[0];
    const float* EN3 = (const float*)d_in[1];
    const float* EN2 = (const float*)d_in[2];
    const float* EN1 = (const float*)d_in[3];
    const float* DE3 = (const float*)d_in[4];
    const float* DE2 = (const float*)d_in[5];
    const float* DE1 = (const float*)d_in[6];
    float* out = (float*)d_out;

    float *bufA, *bufB, *bufC;
    cudaGetSymbolAddress((void**)&bufA, g_bufA);
    cudaGetSymbolAddress((void**)&bufB, g_bufB);
    cudaGetSymbolAddress((void**)&bufC, g_bufC);

    // Encode config: K=128, M=48, KB=32, 16x8 threads, thread tile 8x6 (128 thr)
    // Decode config: K=48,  M=128, KB=24, 16x16 threads, thread tile 8x8 (256 thr)
    // (single decode ordering == averaged result exactly; contractions commute)

    // S1: contract d.  x[bc][d][h,w] (J=16384) -> bufA = [bc][h][w][p]
    gemm_stage<128, 48, 32, 16, 8, 8, 6><<<dim3(128, 1, BC), 128>>>(x,    EN3, bufA, 16384);
    // S2: contract h.  bufA[bc][h][w,p] (J=6144) -> bufB = [bc][w][p][q]
    gemm_stage<128, 48, 32, 16, 8, 8, 6><<<dim3(48, 1, BC), 128>>>(bufA, EN2, bufB, 6144);
    // S3: contract w.  bufB[bc][w][p,q] (J=2304) -> bufC = enc = [bc][p][q][r]
    gemm_stage<128, 48, 32, 16, 8, 8, 6><<<dim3(18, 1, BC), 128>>>(bufB, EN1, bufC, 2304);

    // S4: contract p.  enc[bc][p][q,r] (J=2304) -> bufB = [bc][q][r][d]
    gemm_stage<48, 128, 24, 16, 16, 8, 8><<<dim3(18, 1, BC), 256>>>(bufC, DE3, bufB, 2304);
    // S5: contract q.  bufB[bc][q][r,d] (J=6144) -> bufA = [bc][r][d][h]
    gemm_stage<48, 128, 24, 16, 16, 8, 8><<<dim3(48, 1, BC), 256>>>(bufB, DE2, bufA, 6144);
    // S6: contract r.  bufA[bc][r][d,h] (J=16384) -> out = [b][c][d][h][w]
    gemm_stage<48, 128, 24, 16, 16, 8, 8><<<dim3(128, 1, BC), 256>>>(bufA, DE1, out, 16384);
}

// round 3
// speedup vs baseline: 1.5749x; 1.3030x over previous
#include <cuda_runtime.h>
#include <cstdint>

// Problem constants: B*C = 16, L = 128, N = 48
#define BC 16

// Scratch (device globals; allocation in kernel_launch is forbidden)
__device__ float g_bufA[(size_t)BC * 16384 * 48];
__device__ float g_bufB[(size_t)BC * 6144  * 48];
__device__ float g_bufC[(size_t)BC * 2304  * 48];

__device__ __forceinline__ uint32_t f32_to_tf32(float v) {
    uint32_t r;
    asm("cvt.rna.tf32.f32 %0, %1;" : "=r"(r) : "f"(v));
    return r;
}

__device__ __forceinline__ void mma_tf32(float d[4], const uint32_t a[4], const uint32_t b[2]) {
    asm volatile(
        "mma.sync.aligned.m16n8k8.row.col.f32.tf32.tf32.f32 "
        "{%0,%1,%2,%3}, {%4,%5,%6,%7}, {%8,%9}, {%0,%1,%2,%3};"
        : "+f"(d[0]), "+f"(d[1]), "+f"(d[2]), "+f"(d[3])
        : "r"(a[0]), "r"(a[1]), "r"(a[2]), "r"(a[3]), "r"(b[0]), "r"(b[1]));
}

// out[b][j][m] = sum_k in[b][k][j] * W[k][m]     (3xTF32 via m16n8k8)
// in : [batch][K][J] (j contig);  W : [K][M] (m contig);  out : [batch][J][M]
// Block: 32*WJ*WM threads. Warp (wj,wm) computes j-strip [wj*16,+16) x m-range
// [wm*M/WM, +M/WM). BJ = WJ*16 j's per block. grid=(J/BJ, 1, batch).
// Smem (dynamic): WsHi[K*WSTR], WsLo[K*WSTR], AsHi[KB*(BJ+4)], AsLo[KB*(BJ+4)].
template<int K, int KB, int M, int WSTR, int WJ, int WM>
__global__ void __launch_bounds__(32 * WJ * WM) mma_stage(
    const float* __restrict__ in, const float* __restrict__ W,
    float* __restrict__ out, int J)
{
    constexpr int BJ  = WJ * 16;
    constexpr int BJP = BJ + 4;
    constexpr int NT  = 32 * WJ * WM;
    constexpr int NTILE = M / (8 * WM);   // 8-wide n-tiles per warp

    extern __shared__ float sm[];
    float* WsHi = sm;
    float* WsLo = WsHi + K * WSTR;
    float* AsHi = WsLo + K * WSTR;
    float* AsLo = AsHi + KB * BJP;

    const int tid  = threadIdx.x;
    const int lane = tid & 31;
    const int warp = tid >> 5;
    const int wj   = warp % WJ;
    const int wm   = warp / WJ;
    const int gid  = lane >> 2;    // 0..7
    const int tq   = lane & 3;     // 0..3
    const int b    = blockIdx.z;
    const int m0   = wm * (M / WM);

    // ---- stage W hi/lo (once per block) ----
    for (int i = tid; i < K * M; i += NT) {
        const int k = i / M, m = i % M;
        const float v  = W[i];
        const float hf = __uint_as_float(f32_to_tf32(v));
        WsHi[k * WSTR + m] = hf;
        WsLo[k * WSTR + m] = __uint_as_float(f32_to_tf32(v - hf));
    }

    float acc[NTILE][4];
#pragma unroll
    for (int t = 0; t < NTILE; t++)
#pragma unroll
        for (int r = 0; r < 4; r++) acc[t][r] = 0.0f;

    const float* inb = in + (size_t)b * K * J + (size_t)blockIdx.x * BJ;

#pragma unroll 1
    for (int kp = 0; kp < K; kp += KB) {
        __syncthreads();
        // ---- load + split A panel: KB x BJ (coalesced float4) ----
#pragma unroll
        for (int i = tid; i < KB * BJ / 4; i += NT) {
            const int r = i / (BJ / 4);
            const int c = (i % (BJ / 4)) * 4;
            float4 v = *reinterpret_cast<const float4*>(&inb[(size_t)(kp + r) * J + c]);
            float4 hi, lo;
            hi.x = __uint_as_float(f32_to_tf32(v.x)); lo.x = __uint_as_float(f32_to_tf32(v.x - hi.x));
            hi.y = __uint_as_float(f32_to_tf32(v.y)); lo.y = __uint_as_float(f32_to_tf32(v.y - hi.y));
            hi.z = __uint_as_float(f32_to_tf32(v.z)); lo.z = __uint_as_float(f32_to_tf32(v.z - hi.z));
            hi.w = __uint_as_float(f32_to_tf32(v.w)); lo.w = __uint_as_float(f32_to_tf32(v.w - hi.w));
            *reinterpret_cast<float4*>(&AsHi[r * BJP + c]) = hi;
            *reinterpret_cast<float4*>(&AsLo[r * BJP + c]) = lo;
        }
        __syncthreads();

#pragma unroll
        for (int kc = 0; kc < KB; kc += 8) {
            // A fragments (conflict-free: BJP%32 == 4)
            uint32_t ah[4], al[4];
            const int jb = wj * 16;
            ah[0] = __float_as_uint(AsHi[(kc + tq) * BJP + jb + gid]);
            ah[1] = __float_as_uint(AsHi[(kc + tq) * BJP + jb + gid + 8]);
            ah[2] = __float_as_uint(AsHi[(kc + tq + 4) * BJP + jb + gid]);
            ah[3] = __float_as_uint(AsHi[(kc + tq + 4) * BJP + jb + gid + 8]);
            al[0] = __float_as_uint(AsLo[(kc + tq) * BJP + jb + gid]);
            al[1] = __float_as_uint(AsLo[(kc + tq) * BJP + jb + gid + 8]);
            al[2] = __float_as_uint(AsLo[(kc + tq + 4) * BJP + jb + gid]);
            al[3] = __float_as_uint(AsLo[(kc + tq + 4) * BJP + jb + gid + 8]);

#pragma unroll
            for (int nt = 0; nt < NTILE; nt++) {
                const int mb = m0 + nt * 8;
                uint32_t bh[2], bl[2];
                bh[0] = __float_as_uint(WsHi[(kp + kc + tq) * WSTR + mb + gid]);
                bh[1] = __float_as_uint(WsHi[(kp + kc + tq + 4) * WSTR + mb + gid]);
                bl[0] = __float_as_uint(WsLo[(kp + kc + tq) * WSTR + mb + gid]);
                bl[1] = __float_as_uint(WsLo[(kp + kc + tq + 4) * WSTR + mb + gid]);
                mma_tf32(acc[nt], al, bh);   // small terms first
                mma_tf32(acc[nt], ah, bl);
                mma_tf32(acc[nt], ah, bh);
            }
        }
    }

    // ---- write out: rows j0+gid / +8, cols mb+2*tq / +1 ----
    const int j0 = blockIdx.x * BJ + wj * 16;
    float* op = out + (size_t)b * J * M + (size_t)(j0 + gid) * M;
#pragma unroll
    for (int nt = 0; nt < NTILE; nt++) {
        const int mb = m0 + nt * 8 + 2 * tq;
        *reinterpret_cast<float2*>(&op[mb])            = make_float2(acc[nt][0], acc[nt][1]);
        *reinterpret_cast<float2*>(&op[8 * M + mb])    = make_float2(acc[nt][2], acc[nt][3]);
    }
}

extern "C" void kernel_launch(void* const* d_in, const int* in_sizes, int n_in,
                              void* d_out, int out_size)
{
    const float* x   = (const float*)d_in[0];
    const float* EN3 = (const float*)d_in[1];
    const float* EN2 = (const float*)d_in[2];
    const float* EN1 = (const float*)d_in[3];
    const float* DE3 = (const float*)d_in[4];
    const float* DE2 = (const float*)d_in[5];
    const float* DE1 = (const float*)d_in[6];
    float* out = (float*)d_out;

    float *bufA, *bufB, *bufC;
    cudaGetSymbolAddress((void**)&bufA, g_bufA);
    cudaGetSymbolAddress((void**)&bufB, g_bufB);
    cudaGetSymbolAddress((void**)&bufC, g_bufC);

    // Encode: K=128, M=48, KB=32, 8 warps x (16j, full 48m). WSTR=56 (conflict-free).
    // Decode: K=48,  M=128, KB=48, (4j x 2m) warps, 16j x 64m each. WSTR=136.
    constexpr int ENC_SMEM = (128 * 56 * 2 + 32 * 132 * 2) * 4;   // 91136 B
    constexpr int DEC_SMEM = (48 * 136 * 2 + 48 * 68 * 2) * 4;    // 78336 B

    auto enc = mma_stage<128, 32, 48, 56, 8, 1>;
    auto dec = mma_stage<48, 48, 128, 136, 4, 2>;
    cudaFuncSetAttribute(enc, cudaFuncAttributeMaxDynamicSharedMemorySize, ENC_SMEM);
    cudaFuncSetAttribute(dec, cudaFuncAttributeMaxDynamicSharedMemorySize, DEC_SMEM);

    // (single decode ordering == averaged result exactly; mode contractions commute)

    // S1: contract d.  x[bc][d][hw]   (J=16384) -> bufA = [bc][h][w][p]
    enc<<<dim3(128, 1, BC), 256, ENC_SMEM>>>(x,    EN3, bufA, 16384);
    // S2: contract h.  bufA[bc][h][wp] (J=6144) -> bufB = [bc][w][p][q]
    enc<<<dim3(48, 1, BC), 256, ENC_SMEM>>>(bufA, EN2, bufB, 6144);
    // S3: contract w.  bufB[bc][w][pq] (J=2304) -> bufC = enc = [bc][p][q][r]
    enc<<<dim3(18, 1, BC), 256, ENC_SMEM>>>(bufB, EN1, bufC, 2304);

    // S4: contract p.  enc[bc][p][qr]  (J=2304) -> bufB = [bc][q][r][d]
    dec<<<dim3(36, 1, BC), 256, DEC_SMEM>>>(bufC, DE3, bufB, 2304);
    // S5: contract q.  bufB[bc][q][rd] (J=6144) -> bufA = [bc][r][d][h]
    dec<<<dim3(96, 1, BC), 256, DEC_SMEM>>>(bufB, DE2, bufA, 6144);
    // S6: contract r.  bufA[bc][r][dh] (J=16384) -> out = [b][c][d][h][w]
    dec<<<dim3(256, 1, BC), 256, DEC_SMEM>>>(bufA, DE1, out, 16384);
}

// round 4
// speedup vs baseline: 2.2028x; 1.3986x over previous
#include <cuda_runtime.h>
#include <cstdint>

// Problem constants: B*C = 16, L = 128, N = 48
#define BC 16

// Scratch (device globals; allocation in kernel_launch is forbidden)
__device__ float g_bufA[(size_t)BC * 16384 * 48];
__device__ float g_bufB[(size_t)BC * 6144  * 48];
__device__ float g_bufC[(size_t)BC * 2304  * 48];

// Precomputed W fragments: 6 matrices (EN3,EN2,EN1,DE3,DE2,DE1).
// Each matrix has K/8 * M/8 * 32 lane-slots = 3072 float2 (hi) + 3072 (lo).
__device__ float2 g_wfHi[6][3072];
__device__ float2 g_wfLo[6][3072];

__device__ __forceinline__ float tf32r(float v) {
    uint32_t r; asm("cvt.rna.tf32.f32 %0, %1;" : "=r"(r) : "f"(v));
    return __uint_as_float(r);
}

__device__ __forceinline__ void mma_tf32(float d[4], const float4& a, const float2& b) {
    asm volatile(
        "mma.sync.aligned.m16n8k8.row.col.f32.tf32.tf32.f32 "
        "{%0,%1,%2,%3}, {%4,%5,%6,%7}, {%8,%9}, {%0,%1,%2,%3};"
        : "+f"(d[0]), "+f"(d[1]), "+f"(d[2]), "+f"(d[3])
        : "r"(__float_as_uint(a.x)), "r"(__float_as_uint(a.y)),
          "r"(__float_as_uint(a.z)), "r"(__float_as_uint(a.w)),
          "r"(__float_as_uint(b.x)), "r"(__float_as_uint(b.y)));
}

// Build mma-B-fragment layout for all 6 weight matrices (hi/lo tf32 split).
// frag[(kc*NMT + mt)*32 + lane] = float2( W[kc*8+tq][mt*8+gid], W[kc*8+tq+4][mt*8+gid] )
__global__ void prep_wfrag(const float* __restrict__ W0, const float* __restrict__ W1,
                           const float* __restrict__ W2, const float* __restrict__ W3,
                           const float* __restrict__ W4, const float* __restrict__ W5)
{
    const int m = blockIdx.y;
    const float* W = (m==0)?W0:(m==1)?W1:(m==2)?W2:(m==3)?W3:(m==4)?W4:W5;
    const int M   = (m < 3) ? 48 : 128;
    const int NMT = M / 8;
    const int t = blockIdx.x * blockDim.x + threadIdx.x;   // 0..3071
    const int rem  = t % (NMT * 32);
    const int kc   = t / (NMT * 32);
    const int mt   = rem / 32;
    const int lane = rem % 32;
    const int tq = lane & 3, gid = lane >> 2;
    const float v0 = W[(kc*8 + tq)     * M + mt*8 + gid];
    const float v1 = W[(kc*8 + tq + 4) * M + mt*8 + gid];
    const float h0 = tf32r(v0), h1 = tf32r(v1);
    g_wfHi[m][t] = make_float2(h0, h1);
    g_wfLo[m][t] = make_float2(tf32r(v0 - h0), tf32r(v1 - h1));
}

// out[b][j][m] = sum_k in[b][k][j] * W[k][m]   (3xTF32, m16n8k8)
// NW warps: MWARPS m-warps (NTILE 8-wide m-tiles each; MWARPS*NTILE*8 == M),
// NW/MWARPS j-warp groups, each owning NSL = NS/(NW/MWARPS) 16-j strips.
// A panel (full K x BJ, hi+lo) staged ONCE in smem in fragment-ready layout:
// one LDS.128 yields a complete mma A-fragment. Single __syncthreads.
template<int K, int M, int NW, int NS, int MWARPS, int NTILE>
__global__ void __launch_bounds__(NW * 32) mma_stage(
    const float* __restrict__ in, const float2* __restrict__ wHi,
    const float2* __restrict__ wLo, float* __restrict__ out, int J)
{
    constexpr int KC  = K / 8;
    constexpr int NMT = M / 8;
    constexpr int BJ  = NS * 16;
    constexpr int JW  = NW / MWARPS;
    constexpr int NSL = NS / JW;

    __shared__ float4 AsHi[KC * NS * 32];
    __shared__ float4 AsLo[KC * NS * 32];

    const int tid  = threadIdx.x;
    const int lane = tid & 31, warp = tid >> 5;
    const int tq = lane & 3, gid = lane >> 2;
    const int b  = blockIdx.z;
    const int j0 = blockIdx.x * BJ;
    const int mt0 = (warp % MWARPS) * NTILE;
    const int s0  = (warp / MWARPS) * NSL;

    // ---- stage A fragments (lane-owns-slot: gather what this lane will consume) ----
    const float* inb = in + (size_t)b * K * J + j0;
#pragma unroll
    for (int t = warp; t < KC * NS; t += NW) {
        const int kcb = t / NS, s = t % NS;
        const float* p = inb + (size_t)(kcb * 8 + tq) * J + s * 16 + gid;
        const float v00 = p[0],             v01 = p[8];
        const float v10 = p[(size_t)4 * J], v11 = p[(size_t)4 * J + 8];
        const float h0 = tf32r(v00), h1 = tf32r(v01), h2 = tf32r(v10), h3 = tf32r(v11);
        AsHi[t * 32 + lane] = make_float4(h0, h1, h2, h3);
        AsLo[t * 32 + lane] = make_float4(tf32r(v00 - h0), tf32r(v01 - h1),
                                          tf32r(v10 - h2), tf32r(v11 - h3));
    }
    __syncthreads();

    // ---- compute: per strip, K-loop of fragment mmas ----
#pragma unroll
    for (int s = s0; s < s0 + NSL; s++) {
        float acc[NTILE][4];
#pragma unroll
        for (int nt = 0; nt < NTILE; nt++)
#pragma unroll
            for (int r = 0; r < 4; r++) acc[nt][r] = 0.0f;

#pragma unroll
        for (int kc = 0; kc < KC; kc++) {
            const float4 ah = AsHi[(kc * NS + s) * 32 + lane];
            const float4 al = AsLo[(kc * NS + s) * 32 + lane];
#pragma unroll
            for (int nt = 0; nt < NTILE; nt++) {
                const float2 bh = __ldg(&wHi[(kc * NMT + mt0 + nt) * 32 + lane]);
                const float2 bl = __ldg(&wLo[(kc * NMT + mt0 + nt) * 32 + lane]);
                mma_tf32(acc[nt], al, bh);   // small cross terms first
                mma_tf32(acc[nt], ah, bl);
                mma_tf32(acc[nt], ah, bh);
            }
        }

        float* op = out + (size_t)b * J * M + (size_t)(j0 + s * 16 + gid) * M;
#pragma unroll
        for (int nt = 0; nt < NTILE; nt++) {
            const int mc = (mt0 + nt) * 8 + 2 * tq;
            *reinterpret_cast<float2*>(&op[mc]) =
                make_float2(acc[nt][0], acc[nt][1]);
            *reinterpret_cast<float2*>(&op[(size_t)8 * M + mc]) =
                make_float2(acc[nt][2], acc[nt][3]);
        }
    }
}

extern "C" void kernel_launch(void* const* d_in, const int* in_sizes, int n_in,
                              void* d_out, int out_size)
{
    const float* x   = (const float*)d_in[0];
    const float* EN3 = (const float*)d_in[1];
    const float* EN2 = (const float*)d_in[2];
    const float* EN1 = (const float*)d_in[3];
    const float* DE3 = (const float*)d_in[4];
    const float* DE2 = (const float*)d_in[5];
    const float* DE1 = (const float*)d_in[6];
    float* out = (float*)d_out;

    float *bufA, *bufB, *bufC;
    cudaGetSymbolAddress((void**)&bufA, g_bufA);
    cudaGetSymbolAddress((void**)&bufB, g_bufB);
    cudaGetSymbolAddress((void**)&bufC, g_bufC);
    float2 *wfHi, *wfLo;
    cudaGetSymbolAddress((void**)&wfHi, g_wfHi);
    cudaGetSymbolAddress((void**)&wfLo, g_wfLo);

    // Build W fragments (hi/lo tf32) for all 6 matrices.
    prep_wfrag<<<dim3(24, 6), 128>>>(EN3, EN2, EN1, DE3, DE2, DE1);

    // Encode: K=128, M=48. 4 warps (2 m-warps x NTILE=3, 2 j-warps x 1 strip), BJ=32.
    // Decode: K=48, M=128. 8 warps (8 m-warps x NTILE=2), BJ=64, 4 strips each.
    // (single decode ordering == averaged result exactly; mode contractions commute)
    auto enc = mma_stage<128, 48, 4, 2, 2, 3>;
    auto dec = mma_stage<48, 128, 8, 4, 8, 2>;

    // S1: contract d.  x[bc][d][hw]   (J=16384) -> bufA = [bc][h][w][p]
    enc<<<dim3(512, 1, BC), 128>>>(x,    wfHi + 0*3072, wfLo + 0*3072, bufA, 16384);
    // S2: contract h.  bufA[bc][h][wp] (J=6144) -> bufB = [bc][w][p][q]
    enc<<<dim3(192, 1, BC), 128>>>(bufA, wfHi + 1*3072, wfLo + 1*3072, bufB, 6144);
    // S3: contract w.  bufB[bc][w][pq] (J=2304) -> bufC = enc = [bc][p][q][r]
    enc<<<dim3(72, 1, BC), 128>>>(bufB, wfHi + 2*3072, wfLo + 2*3072, bufC, 2304);

    // S4: contract p.  enc[bc][p][qr]  (J=2304) -> bufB = [bc][q][r][d]
    dec<<<dim3(36, 1, BC), 256>>>(bufC, wfHi + 3*3072, wfLo + 3*3072, bufB, 2304);
    // S5: contract q.  bufB[bc][q][rd] (J=6144) -> bufA = [bc][r][d][h]
    dec<<<dim3(96, 1, BC), 256>>>(bufB, wfHi + 4*3072, wfLo + 4*3072, bufA, 6144);
    // S6: contract r.  bufA[bc][r][dh] (J=16384) -> out = [b][c][d][h][w]
    dec<<<dim3(256, 1, BC), 256>>>(bufA, wfHi + 5*3072, wfLo + 5*3072, out, 16384);
}